// round 1
// baseline (speedup 1.0000x reference)
#include <cuda_runtime.h>
#include <cstdint>

// Problem constants (fixed by the dataset)
#define NN     100000   // nodes
#define HH     128      // hidden
#define TT     32       // transitivity size
#define MDIM   16       // mask dim
#define KSTEPS 3        // propagation rounds
#define ES     600000   // spatial edges
#define ED     600000   // dom edges

// ---------------- scratch (static __device__, no allocs) ----------------
__device__ __align__(16) float g_Ps[NN * TT];        // x @ W_trans[:H]
__device__ __align__(16) float g_Pd[NN * TT];        // x @ W_trans[H:]
__device__ float g_ew_s[ES];
__device__ float g_ew_d[ED];
__device__ __align__(16) float g_mpos[2][NN * MDIM];
__device__ __align__(16) float g_mdom[2][NN * MDIM];

// ---------------- kernel 1: node projections -----------------------------
// One thread per node; W_trans (256x32 = 32KB) staged in shared (broadcast LDS).
__global__ void proj_kernel(const float* __restrict__ x,
                            const float* __restrict__ Wt) {
    __shared__ float Ws[2 * HH * TT];
    for (int i = threadIdx.x; i < 2 * HH * TT; i += blockDim.x) Ws[i] = Wt[i];
    __syncthreads();

    int n = blockIdx.x * blockDim.x + threadIdx.x;
    if (n >= NN) return;

    float accS[TT], accD[TT];
#pragma unroll
    for (int t = 0; t < TT; t++) { accS[t] = 0.f; accD[t] = 0.f; }

    const float4* x4 = reinterpret_cast<const float4*>(x + (size_t)n * HH);
    for (int h4 = 0; h4 < HH / 4; h4++) {
        float4 v = x4[h4];
        float xv[4] = {v.x, v.y, v.z, v.w};
#pragma unroll
        for (int j = 0; j < 4; j++) {
            int h = h4 * 4 + j;
            const float* wS = &Ws[h * TT];
            const float* wD = &Ws[(HH + h) * TT];
#pragma unroll
            for (int t = 0; t < TT; t++) {
                accS[t] = fmaf(xv[j], wS[t], accS[t]);
                accD[t] = fmaf(xv[j], wD[t], accD[t]);
            }
        }
    }

    float* ps = &g_Ps[(size_t)n * TT];
    float* pd = &g_Pd[(size_t)n * TT];
#pragma unroll
    for (int t = 0; t < TT; t += 4) {
        *reinterpret_cast<float4*>(ps + t) =
            make_float4(accS[t], accS[t + 1], accS[t + 2], accS[t + 3]);
        *reinterpret_cast<float4*>(pd + t) =
            make_float4(accD[t], accD[t + 1], accD[t + 2], accD[t + 3]);
    }
}

// ---------------- kernel 2: init mask buffers -----------------------------
__global__ void init_kernel(const float* __restrict__ mask) {
    int i = blockIdx.x * blockDim.x + threadIdx.x;   // float4 index
    const int n4 = NN * MDIM / 4;
    if (i >= n4) return;
    float4 v = reinterpret_cast<const float4*>(mask)[i];
    reinterpret_cast<float4*>(g_mpos[0])[i] = v;
    reinterpret_cast<float4*>(g_mdom[0])[i] = v;
}

// ---------------- kernel 3: per-edge gate (both edge sets) ----------------
// One warp per edge: lane t handles transitivity channel t.
__global__ void ew_kernel(const int* __restrict__ si, const int* __restrict__ di,
                          const float* __restrict__ sattr, const float* __restrict__ dattr,
                          const float* __restrict__ b_trans,
                          const float* __restrict__ Wpos, const float* __restrict__ bpos,
                          const float* __restrict__ Wdom, const float* __restrict__ bdom) {
    int warp = (blockIdx.x * blockDim.x + threadIdx.x) >> 5;
    int lane = threadIdx.x & 31;
    if (warp >= ES + ED) return;

    bool spatial = (warp < ES);
    int e = spatial ? warp : warp - ES;
    const int* eidx = spatial ? si : di;
    int nE = spatial ? ES : ED;
    int src = eidx[e];
    int dst = eidx[nE + e];

    float s = g_Ps[(size_t)src * TT + lane] + g_Pd[(size_t)dst * TT + lane] + b_trans[lane];
    float th = tanhf(s);
    float w = spatial ? Wpos[4 + lane] : Wdom[1 + lane];
    float part = th * w;

    if (spatial) {
        if (lane < 4) part += sattr[(size_t)e * 4 + lane] * Wpos[lane];
    } else {
        if (lane == 0) part += dattr[e] * Wdom[0];
    }

#pragma unroll
    for (int o = 16; o; o >>= 1) part += __shfl_xor_sync(0xFFFFFFFFu, part, o);

    if (lane == 0) {
        float logit = part + (spatial ? bpos[0] : bdom[0]);
        float ew = 1.f / (1.f + __expf(-logit));
        if (spatial) g_ew_s[e] = ew; else g_ew_d[e] = ew;
    }
}

// ---------------- kernel 4: copy m_cur -> m_next (both branches) ----------
__global__ void copy_kernel(int cur) {
    int i = blockIdx.x * blockDim.x + threadIdx.x;   // float4 index
    const int n4 = NN * MDIM / 4;
    if (i >= n4) return;
    int nxt = cur ^ 1;
    reinterpret_cast<float4*>(g_mpos[nxt])[i] = reinterpret_cast<const float4*>(g_mpos[cur])[i];
    reinterpret_cast<float4*>(g_mdom[nxt])[i] = reinterpret_cast<const float4*>(g_mdom[cur])[i];
}

// ---------------- kernel 5: one propagation round (both edge sets) --------
// 16 threads per edge (one per mask channel); coalesced 64B gather + RED.max.
__global__ void prop_kernel(const int* __restrict__ si, const int* __restrict__ di, int cur) {
    long long t = (long long)blockIdx.x * blockDim.x + threadIdx.x;
    long long e = t >> 4;
    int c = (int)(t & 15);
    if (e >= (long long)(ES + ED)) return;
    int nxt = cur ^ 1;

    if (e < ES) {
        int ei = (int)e;
        int src = si[ei];
        int dst = si[ES + ei];
        float ew = g_ew_s[ei];
        float v = g_mpos[cur][(size_t)src * MDIM + c] * ew;
        atomicMax(reinterpret_cast<unsigned int*>(&g_mpos[nxt][(size_t)dst * MDIM + c]),
                  __float_as_uint(v));
    } else {
        int ei = (int)(e - ES);
        int src = di[ei];
        int dst = di[ED + ei];
        float ew = g_ew_d[ei];
        float v = g_mdom[cur][(size_t)src * MDIM + c] * ew;
        atomicMax(reinterpret_cast<unsigned int*>(&g_mdom[nxt][(size_t)dst * MDIM + c]),
                  __float_as_uint(v));
    }
}

// ---------------- kernel 6: final max ------------------------------------
__global__ void final_kernel(const float* __restrict__ mask, float* __restrict__ out, int fin) {
    int i = blockIdx.x * blockDim.x + threadIdx.x;   // float4 index
    const int n4 = NN * MDIM / 4;
    if (i >= n4) return;
    float4 m  = reinterpret_cast<const float4*>(mask)[i];
    float4 p  = reinterpret_cast<const float4*>(g_mpos[fin])[i];
    float4 d  = reinterpret_cast<const float4*>(g_mdom[fin])[i];
    float4 r;
    r.x = fmaxf(m.x, fmaxf(p.x, d.x));
    r.y = fmaxf(m.y, fmaxf(p.y, d.y));
    r.z = fmaxf(m.z, fmaxf(p.z, d.z));
    r.w = fmaxf(m.w, fmaxf(p.w, d.w));
    reinterpret_cast<float4*>(out)[i] = r;
}

// ---------------- launch -------------------------------------------------
extern "C" void kernel_launch(void* const* d_in, const int* in_sizes, int n_in,
                              void* d_out, int out_size) {
    const float* x      = (const float*)d_in[0];
    const float* mask   = (const float*)d_in[1];
    const int*   si     = (const int*)d_in[2];
    const int*   di     = (const int*)d_in[3];
    const float* sattr  = (const float*)d_in[4];
    const float* dattr  = (const float*)d_in[5];
    const float* Wt     = (const float*)d_in[6];
    const float* bt     = (const float*)d_in[7];
    const float* Wpos   = (const float*)d_in[8];
    const float* bpos   = (const float*)d_in[9];
    const float* Wdom   = (const float*)d_in[10];
    const float* bdom   = (const float*)d_in[11];
    float* out = (float*)d_out;

    // 1. node projections (shared by both branches)
    proj_kernel<<<(NN + 255) / 256, 256>>>(x, Wt);

    // 2. init mask double-buffers
    const int n4 = NN * MDIM / 4;
    init_kernel<<<(n4 + 255) / 256, 256>>>(mask);

    // 3. per-edge gates (both edge sets in one launch)
    {
        long long warps = (long long)ES + ED;
        long long threads = warps * 32;
        int blk = 256;
        long long grid = (threads + blk - 1) / blk;
        ew_kernel<<<(unsigned)grid, blk>>>(si, di, sattr, dattr, bt, Wpos, bpos, Wdom, bdom);
    }

    // 4. K propagation rounds
    int cur = 0;
    for (int r = 0; r < KSTEPS; r++) {
        copy_kernel<<<(n4 + 255) / 256, 256>>>(cur);
        long long threads = (long long)(ES + ED) * MDIM;
        int blk = 256;
        long long grid = (threads + blk - 1) / blk;
        prop_kernel<<<(unsigned)grid, blk>>>(si, di, cur);
        cur ^= 1;
    }

    // 5. final elementwise max
    final_kernel<<<(n4 + 255) / 256, 256>>>(mask, out, cur);
}

// round 2
// speedup vs baseline: 1.2184x; 1.2184x over previous
#include <cuda_runtime.h>
#include <cstdint>

// Problem constants (fixed by the dataset)
#define NN     100000   // nodes
#define HH     128      // hidden
#define TT     32       // transitivity size
#define MDIM   16       // mask dim
#define KSTEPS 3        // propagation rounds
#define ES     600000   // spatial edges
#define ED     600000   // dom edges

// ---------------- scratch (static __device__, no allocs) ----------------
__device__ __align__(16) float g_Ps[NN * TT];        // x @ W_trans[:H]
__device__ __align__(16) float g_Pd[NN * TT];        // x @ W_trans[H:]
__device__ float g_ew_s[ES];
__device__ float g_ew_d[ED];
__device__ __align__(16) float g_mpos[2][NN * MDIM];
__device__ __align__(16) float g_mdom[2][NN * MDIM];

// ---------------- kernel 1: node projections -----------------------------
// One thread per node; W_trans (256x32 = 32KB) staged in shared (broadcast LDS).
__global__ void proj_kernel(const float* __restrict__ x,
                            const float* __restrict__ Wt) {
    __shared__ float Ws[2 * HH * TT];
    for (int i = threadIdx.x; i < 2 * HH * TT; i += blockDim.x) Ws[i] = Wt[i];
    __syncthreads();

    int n = blockIdx.x * blockDim.x + threadIdx.x;
    if (n >= NN) return;

    float accS[TT], accD[TT];
#pragma unroll
    for (int t = 0; t < TT; t++) { accS[t] = 0.f; accD[t] = 0.f; }

    const float4* x4 = reinterpret_cast<const float4*>(x + (size_t)n * HH);
    for (int h4 = 0; h4 < HH / 4; h4++) {
        float4 v = x4[h4];
        float xv[4] = {v.x, v.y, v.z, v.w};
#pragma unroll
        for (int j = 0; j < 4; j++) {
            int h = h4 * 4 + j;
            const float* wS = &Ws[h * TT];
            const float* wD = &Ws[(HH + h) * TT];
#pragma unroll
            for (int t = 0; t < TT; t++) {
                accS[t] = fmaf(xv[j], wS[t], accS[t]);
                accD[t] = fmaf(xv[j], wD[t], accD[t]);
            }
        }
    }

    float* ps = &g_Ps[(size_t)n * TT];
    float* pd = &g_Pd[(size_t)n * TT];
#pragma unroll
    for (int t = 0; t < TT; t += 4) {
        *reinterpret_cast<float4*>(ps + t) =
            make_float4(accS[t], accS[t + 1], accS[t + 2], accS[t + 3]);
        *reinterpret_cast<float4*>(pd + t) =
            make_float4(accD[t], accD[t + 1], accD[t + 2], accD[t + 3]);
    }
}

// ---------------- kernel 2: init mask buffers -----------------------------
__global__ void init_kernel(const float* __restrict__ mask) {
    int i = blockIdx.x * blockDim.x + threadIdx.x;   // float4 index
    const int n4 = NN * MDIM / 4;
    if (i >= n4) return;
    float4 v = reinterpret_cast<const float4*>(mask)[i];
    reinterpret_cast<float4*>(g_mpos[0])[i] = v;
    reinterpret_cast<float4*>(g_mdom[0])[i] = v;
}

// ---------------- kernel 3: per-edge gate (both edge sets) ----------------
// One warp per edge: lane t handles transitivity channel t. MUFU.TANH fast path.
__device__ __forceinline__ float fast_tanh(float s) {
    float r;
    asm("tanh.approx.f32 %0, %1;" : "=f"(r) : "f"(s));
    return r;
}

__global__ void ew_kernel(const int* __restrict__ si, const int* __restrict__ di,
                          const float* __restrict__ sattr, const float* __restrict__ dattr,
                          const float* __restrict__ b_trans,
                          const float* __restrict__ Wpos, const float* __restrict__ bpos,
                          const float* __restrict__ Wdom, const float* __restrict__ bdom) {
    int warp = (blockIdx.x * blockDim.x + threadIdx.x) >> 5;
    int lane = threadIdx.x & 31;
    if (warp >= ES + ED) return;

    bool spatial = (warp < ES);
    int e = spatial ? warp : warp - ES;
    const int* eidx = spatial ? si : di;
    int nE = spatial ? ES : ED;
    int src = eidx[e];
    int dst = eidx[nE + e];

    float s = g_Ps[(size_t)src * TT + lane] + g_Pd[(size_t)dst * TT + lane] + b_trans[lane];
    float th = fast_tanh(s);
    float w = spatial ? Wpos[4 + lane] : Wdom[1 + lane];
    float part = th * w;

    if (spatial) {
        if (lane < 4) part += sattr[(size_t)e * 4 + lane] * Wpos[lane];
    } else {
        if (lane == 0) part += dattr[e] * Wdom[0];
    }

#pragma unroll
    for (int o = 16; o; o >>= 1) part += __shfl_xor_sync(0xFFFFFFFFu, part, o);

    if (lane == 0) {
        float logit = part + (spatial ? bpos[0] : bdom[0]);
        float ew = 1.f / (1.f + __expf(-logit));
        if (spatial) g_ew_s[e] = ew; else g_ew_d[e] = ew;
    }
}

// ---------------- kernel 4: copy m_cur -> m_next (both branches) ----------
__global__ void copy_kernel(int cur) {
    int i = blockIdx.x * blockDim.x + threadIdx.x;   // float4 index
    const int n4 = NN * MDIM / 4;
    if (i >= n4) return;
    int nxt = cur ^ 1;
    reinterpret_cast<float4*>(g_mpos[nxt])[i] = reinterpret_cast<const float4*>(g_mpos[cur])[i];
    reinterpret_cast<float4*>(g_mdom[nxt])[i] = reinterpret_cast<const float4*>(g_mdom[cur])[i];
}

// ---------------- kernel 5: one propagation round (both edge sets) --------
// 4 threads per edge, float4 per thread. Pre-check against the cur dst row:
// nxt starts as an exact copy of cur, so any v <= cur[dst][c] atomic is a
// provable no-op -> skip it. Converts ~75% of REDG into cheap L2 loads.
__global__ void prop_kernel(const int* __restrict__ si, const int* __restrict__ di, int cur) {
    long long t = (long long)blockIdx.x * blockDim.x + threadIdx.x;
    long long q = t >> 2;            // edge id across both sets
    int c4 = (int)(t & 3);           // channel quad 0..3
    if (q >= (long long)(ES + ED)) return;
    int nxt = cur ^ 1;

    const float* mc;
    float* mn;
    int src, dst;
    float ew;
    if (q < ES) {
        int ei = (int)q;
        src = si[ei];
        dst = si[ES + ei];
        ew  = g_ew_s[ei];
        mc  = g_mpos[cur];
        mn  = g_mpos[nxt];
    } else {
        int ei = (int)(q - ES);
        src = di[ei];
        dst = di[ED + ei];
        ew  = g_ew_d[ei];
        mc  = g_mdom[cur];
        mn  = g_mdom[nxt];
    }

    float4 s = *reinterpret_cast<const float4*>(&mc[(size_t)src * MDIM + c4 * 4]);
    float4 d = *reinterpret_cast<const float4*>(&mc[(size_t)dst * MDIM + c4 * 4]);
    unsigned int* dn = reinterpret_cast<unsigned int*>(&mn[(size_t)dst * MDIM + c4 * 4]);

    float v0 = s.x * ew, v1 = s.y * ew, v2 = s.z * ew, v3 = s.w * ew;
    if (v0 > d.x) atomicMax(dn + 0, __float_as_uint(v0));
    if (v1 > d.y) atomicMax(dn + 1, __float_as_uint(v1));
    if (v2 > d.z) atomicMax(dn + 2, __float_as_uint(v2));
    if (v3 > d.w) atomicMax(dn + 3, __float_as_uint(v3));
}

// ---------------- kernel 6: final max ------------------------------------
__global__ void final_kernel(const float* __restrict__ mask, float* __restrict__ out, int fin) {
    int i = blockIdx.x * blockDim.x + threadIdx.x;   // float4 index
    const int n4 = NN * MDIM / 4;
    if (i >= n4) return;
    float4 m  = reinterpret_cast<const float4*>(mask)[i];
    float4 p  = reinterpret_cast<const float4*>(g_mpos[fin])[i];
    float4 d  = reinterpret_cast<const float4*>(g_mdom[fin])[i];
    float4 r;
    r.x = fmaxf(m.x, fmaxf(p.x, d.x));
    r.y = fmaxf(m.y, fmaxf(p.y, d.y));
    r.z = fmaxf(m.z, fmaxf(p.z, d.z));
    r.w = fmaxf(m.w, fmaxf(p.w, d.w));
    reinterpret_cast<float4*>(out)[i] = r;
}

// ---------------- launch -------------------------------------------------
extern "C" void kernel_launch(void* const* d_in, const int* in_sizes, int n_in,
                              void* d_out, int out_size) {
    const float* x      = (const float*)d_in[0];
    const float* mask   = (const float*)d_in[1];
    const int*   si     = (const int*)d_in[2];
    const int*   di     = (const int*)d_in[3];
    const float* sattr  = (const float*)d_in[4];
    const float* dattr  = (const float*)d_in[5];
    const float* Wt     = (const float*)d_in[6];
    const float* bt     = (const float*)d_in[7];
    const float* Wpos   = (const float*)d_in[8];
    const float* bpos   = (const float*)d_in[9];
    const float* Wdom   = (const float*)d_in[10];
    const float* bdom   = (const float*)d_in[11];
    float* out = (float*)d_out;

    // 1. node projections (shared by both branches)
    proj_kernel<<<(NN + 255) / 256, 256>>>(x, Wt);

    // 2. init mask double-buffers
    const int n4 = NN * MDIM / 4;
    init_kernel<<<(n4 + 255) / 256, 256>>>(mask);

    // 3. per-edge gates (both edge sets in one launch)
    {
        long long warps = (long long)ES + ED;
        long long threads = warps * 32;
        int blk = 256;
        long long grid = (threads + blk - 1) / blk;
        ew_kernel<<<(unsigned)grid, blk>>>(si, di, sattr, dattr, bt, Wpos, bpos, Wdom, bdom);
    }

    // 4. K propagation rounds
    int cur = 0;
    for (int r = 0; r < KSTEPS; r++) {
        copy_kernel<<<(n4 + 255) / 256, 256>>>(cur);
        long long threads = (long long)(ES + ED) * 4;   // 4 threads per edge
        int blk = 256;
        long long grid = (threads + blk - 1) / blk;
        prop_kernel<<<(unsigned)grid, blk>>>(si, di, cur);
        cur ^= 1;
    }

    // 5. final elementwise max
    final_kernel<<<(n4 + 255) / 256, 256>>>(mask, out, cur);
}

// round 3
// speedup vs baseline: 2.1569x; 1.7702x over previous
#include <cuda_runtime.h>
#include <cstdint>

#define NN     100000
#define HH     128
#define TT     32
#define MDIM   16
#define KSTEPS 3
#define ES     600000
#define ED     600000

typedef unsigned long long u64;

// ---------------- scratch ----------------
__device__ __align__(16) float g_Ps[NN * TT];
__device__ __align__(16) float g_Pd[NN * TT];
__device__ float g_ew_s[ES];
__device__ float g_ew_d[ED];
__device__ __align__(16) float g_mpos[2][NN * MDIM];
__device__ __align__(16) float g_mdom[2][NN * MDIM];

// ---------------- packed f32x2 helpers ----------------
__device__ __forceinline__ u64 pack2(float lo, float hi) {
    u64 r; asm("mov.b64 %0, {%1, %2};" : "=l"(r) : "f"(lo), "f"(hi)); return r;
}
__device__ __forceinline__ void unpack2(u64 v, float& lo, float& hi) {
    asm("mov.b64 {%0, %1}, %2;" : "=f"(lo), "=f"(hi) : "l"(v));
}
__device__ __forceinline__ u64 fma2(u64 a, u64 b, u64 c) {
    u64 d; asm("fma.rn.f32x2 %0, %1, %2, %3;" : "=l"(d) : "l"(a), "l"(b), "l"(c)); return d;
}
__device__ __forceinline__ float fast_tanh(float s) {
    float r; asm("tanh.approx.f32 %0, %1;" : "=f"(r) : "f"(s)); return r;
}

// ---------------- kernel 1: node projections (2 nodes/thread, f32x2) ------
// P_s = x @ W[:H], P_d = x @ W[H:]; weights staged in shared as f32 pairs.
__global__ void __launch_bounds__(128) proj_kernel(const float* __restrict__ x,
                                                   const float* __restrict__ Wt) {
    __shared__ __align__(16) float Ws[2 * HH * TT];
    for (int i = threadIdx.x; i < 2 * HH * TT; i += blockDim.x) Ws[i] = Wt[i];
    __syncthreads();
    const u64* WsS = reinterpret_cast<const u64*>(Ws);             // [HH][16]
    const u64* WsD = reinterpret_cast<const u64*>(Ws + HH * TT);   // [HH][16]

    int n0 = (blockIdx.x * blockDim.x + threadIdx.x) * 2;
    if (n0 >= NN) return;

    u64 aS0[TT / 2], aS1[TT / 2], aD0[TT / 2], aD1[TT / 2];
#pragma unroll
    for (int t = 0; t < TT / 2; t++) { aS0[t] = 0; aS1[t] = 0; aD0[t] = 0; aD1[t] = 0; }

    const float4* xa = reinterpret_cast<const float4*>(x + (size_t)n0 * HH);
    const float4* xb = reinterpret_cast<const float4*>(x + (size_t)(n0 + 1) * HH);

    for (int h4 = 0; h4 < HH / 4; h4++) {
        float4 va = xa[h4];
        float4 vb = xb[h4];
        float fa[4] = {va.x, va.y, va.z, va.w};
        float fb[4] = {vb.x, vb.y, vb.z, vb.w};
#pragma unroll
        for (int j = 0; j < 4; j++) {
            int h = h4 * 4 + j;
            u64 xa2 = pack2(fa[j], fa[j]);
            u64 xb2 = pack2(fb[j], fb[j]);
            const u64* wS = &WsS[h * (TT / 2)];
            const u64* wD = &WsD[h * (TT / 2)];
#pragma unroll
            for (int t = 0; t < TT / 2; t++) {
                u64 ws = wS[t], wd = wD[t];
                aS0[t] = fma2(xa2, ws, aS0[t]);
                aS1[t] = fma2(xb2, ws, aS1[t]);
                aD0[t] = fma2(xa2, wd, aD0[t]);
                aD1[t] = fma2(xb2, wd, aD1[t]);
            }
        }
    }

#pragma unroll
    for (int t = 0; t < TT / 2; t += 2) {
        float s0l, s0h, s1l, s1h;
        unpack2(aS0[t], s0l, s0h); unpack2(aS0[t + 1], s1l, s1h);
        *reinterpret_cast<float4*>(&g_Ps[(size_t)n0 * TT + t * 2]) = make_float4(s0l, s0h, s1l, s1h);
        unpack2(aS1[t], s0l, s0h); unpack2(aS1[t + 1], s1l, s1h);
        *reinterpret_cast<float4*>(&g_Ps[(size_t)(n0 + 1) * TT + t * 2]) = make_float4(s0l, s0h, s1l, s1h);
        unpack2(aD0[t], s0l, s0h); unpack2(aD0[t + 1], s1l, s1h);
        *reinterpret_cast<float4*>(&g_Pd[(size_t)n0 * TT + t * 2]) = make_float4(s0l, s0h, s1l, s1h);
        unpack2(aD1[t], s0l, s0h); unpack2(aD1[t + 1], s1l, s1h);
        *reinterpret_cast<float4*>(&g_Pd[(size_t)(n0 + 1) * TT + t * 2]) = make_float4(s0l, s0h, s1l, s1h);
    }
}

// ---------------- kernel 2: init mask buffers -----------------------------
__global__ void init_kernel(const float* __restrict__ mask) {
    int i = blockIdx.x * blockDim.x + threadIdx.x;
    const int n4 = NN * MDIM / 4;
    if (i >= n4) return;
    float4 v = reinterpret_cast<const float4*>(mask)[i];
    reinterpret_cast<float4*>(g_mpos[0])[i] = v;
    reinterpret_cast<float4*>(g_mdom[0])[i] = v;
}

// ---------------- kernel 3: per-edge gate (8 lanes/edge) ------------------
__global__ void ew_kernel(const int* __restrict__ si, const int* __restrict__ di,
                          const float* __restrict__ sattr, const float* __restrict__ dattr,
                          const float* __restrict__ b_trans,
                          const float* __restrict__ Wpos, const float* __restrict__ bpos,
                          const float* __restrict__ Wdom, const float* __restrict__ bdom) {
    long long gid = (long long)blockIdx.x * blockDim.x + threadIdx.x;
    long long eg = gid >> 3;       // edge id across both sets
    int sub = (int)(gid & 7);      // 8-lane subgroup position
    if (eg >= (long long)(ES + ED)) return;

    bool spatial = (eg < ES);
    int e = spatial ? (int)eg : (int)(eg - ES);
    const int* eidx = spatial ? si : di;
    int nE = spatial ? ES : ED;
    int src = eidx[e];          // broadcast within the 8-lane group
    int dst = eidx[nE + e];

    float4 ps = *reinterpret_cast<const float4*>(&g_Ps[(size_t)src * TT + sub * 4]);
    float4 pd = *reinterpret_cast<const float4*>(&g_Pd[(size_t)dst * TT + sub * 4]);
    float4 bt = *reinterpret_cast<const float4*>(&b_trans[sub * 4]);

    float t0 = fast_tanh(ps.x + pd.x + bt.x);
    float t1 = fast_tanh(ps.y + pd.y + bt.y);
    float t2 = fast_tanh(ps.z + pd.z + bt.z);
    float t3 = fast_tanh(ps.w + pd.w + bt.w);

    float part;
    if (spatial) {
        float4 w = *reinterpret_cast<const float4*>(&Wpos[4 + sub * 4]);  // 16B-aligned
        part = t0 * w.x + t1 * w.y + t2 * w.z + t3 * w.w;
        if (sub == 0) {
            float4 a = *reinterpret_cast<const float4*>(&sattr[(size_t)e * 4]);
            part += a.x * Wpos[0] + a.y * Wpos[1] + a.z * Wpos[2] + a.w * Wpos[3];
        }
    } else {
        const float* w = &Wdom[1 + sub * 4];   // 4B-aligned only
        part = t0 * w[0] + t1 * w[1] + t2 * w[2] + t3 * w[3];
        if (sub == 0) part += dattr[e] * Wdom[0];
    }

#pragma unroll
    for (int o = 4; o; o >>= 1) part += __shfl_xor_sync(0xFFFFFFFFu, part, o);

    if (sub == 0) {
        float logit = part + (spatial ? bpos[0] : bdom[0]);
        float ew = 1.f / (1.f + __expf(-logit));
        if (spatial) g_ew_s[e] = ew; else g_ew_d[e] = ew;
    }
}

// ---------------- kernel 4: copy m_cur -> m_next --------------------------
__global__ void copy_kernel(int cur) {
    int i = blockIdx.x * blockDim.x + threadIdx.x;
    const int n4 = NN * MDIM / 4;
    if (i >= n4) return;
    int nxt = cur ^ 1;
    reinterpret_cast<float4*>(g_mpos[nxt])[i] = reinterpret_cast<const float4*>(g_mpos[cur])[i];
    reinterpret_cast<float4*>(g_mdom[nxt])[i] = reinterpret_cast<const float4*>(g_mdom[cur])[i];
}

// ---------------- kernel 5: propagation round (filtered atomics) ----------
__global__ void prop_kernel(const int* __restrict__ si, const int* __restrict__ di, int cur) {
    long long t = (long long)blockIdx.x * blockDim.x + threadIdx.x;
    long long q = t >> 2;
    int c4 = (int)(t & 3);
    if (q >= (long long)(ES + ED)) return;
    int nxt = cur ^ 1;

    const float* mc;
    float* mn;
    int src, dst;
    float ew;
    if (q < ES) {
        int ei = (int)q;
        src = si[ei]; dst = si[ES + ei];
        ew = g_ew_s[ei];
        mc = g_mpos[cur]; mn = g_mpos[nxt];
    } else {
        int ei = (int)(q - ES);
        src = di[ei]; dst = di[ED + ei];
        ew = g_ew_d[ei];
        mc = g_mdom[cur]; mn = g_mdom[nxt];
    }

    float4 s = *reinterpret_cast<const float4*>(&mc[(size_t)src * MDIM + c4 * 4]);
    float4 d = *reinterpret_cast<const float4*>(&mc[(size_t)dst * MDIM + c4 * 4]);
    unsigned int* dn = reinterpret_cast<unsigned int*>(&mn[(size_t)dst * MDIM + c4 * 4]);

    float v0 = s.x * ew, v1 = s.y * ew, v2 = s.z * ew, v3 = s.w * ew;
    if (v0 > d.x) atomicMax(dn + 0, __float_as_uint(v0));
    if (v1 > d.y) atomicMax(dn + 1, __float_as_uint(v1));
    if (v2 > d.z) atomicMax(dn + 2, __float_as_uint(v2));
    if (v3 > d.w) atomicMax(dn + 3, __float_as_uint(v3));
}

// ---------------- kernel 6: final max ------------------------------------
__global__ void final_kernel(const float* __restrict__ mask, float* __restrict__ out, int fin) {
    int i = blockIdx.x * blockDim.x + threadIdx.x;
    const int n4 = NN * MDIM / 4;
    if (i >= n4) return;
    float4 m = reinterpret_cast<const float4*>(mask)[i];
    float4 p = reinterpret_cast<const float4*>(g_mpos[fin])[i];
    float4 d = reinterpret_cast<const float4*>(g_mdom[fin])[i];
    float4 r;
    r.x = fmaxf(m.x, fmaxf(p.x, d.x));
    r.y = fmaxf(m.y, fmaxf(p.y, d.y));
    r.z = fmaxf(m.z, fmaxf(p.z, d.z));
    r.w = fmaxf(m.w, fmaxf(p.w, d.w));
    reinterpret_cast<float4*>(out)[i] = r;
}

// ---------------- launch -------------------------------------------------
extern "C" void kernel_launch(void* const* d_in, const int* in_sizes, int n_in,
                              void* d_out, int out_size) {
    const float* x     = (const float*)d_in[0];
    const float* mask  = (const float*)d_in[1];
    const int*   si    = (const int*)d_in[2];
    const int*   di    = (const int*)d_in[3];
    const float* sattr = (const float*)d_in[4];
    const float* dattr = (const float*)d_in[5];
    const float* Wt    = (const float*)d_in[6];
    const float* bt    = (const float*)d_in[7];
    const float* Wpos  = (const float*)d_in[8];
    const float* bpos  = (const float*)d_in[9];
    const float* Wdom  = (const float*)d_in[10];
    const float* bdom  = (const float*)d_in[11];
    float* out = (float*)d_out;

    // 1. node projections (2 nodes/thread)
    proj_kernel<<<(NN / 2 + 127) / 128, 128>>>(x, Wt);

    // 2. init mask double-buffers
    const int n4 = NN * MDIM / 4;
    init_kernel<<<(n4 + 255) / 256, 256>>>(mask);

    // 3. per-edge gates: 8 lanes/edge
    {
        long long threads = (long long)(ES + ED) * 8;
        int blk = 256;
        long long grid = (threads + blk - 1) / blk;
        ew_kernel<<<(unsigned)grid, blk>>>(si, di, sattr, dattr, bt, Wpos, bpos, Wdom, bdom);
    }

    // 4. K propagation rounds
    int cur = 0;
    for (int r = 0; r < KSTEPS; r++) {
        copy_kernel<<<(n4 + 255) / 256, 256>>>(cur);
        long long threads = (long long)(ES + ED) * 4;
        int blk = 256;
        long long grid = (threads + blk - 1) / blk;
        prop_kernel<<<(unsigned)grid, blk>>>(si, di, cur);
        cur ^= 1;
    }

    // 5. final elementwise max
    final_kernel<<<(n4 + 255) / 256, 256>>>(mask, out, cur);
}